// round 3
// baseline (speedup 1.0000x reference)
#include <cuda_runtime.h>

#define BB 512
#define TT 512
#define NS 64

// 2 full-precision fp32 FMAs per instruction (sm_103a packed pipe)
#define FMA2(acc, p, e) \
    asm("fma.rn.f32x2 %0, %1, %2, %0;" : "+l"(acc) : "l"(p), "l"(e))
#define ADD2(out, a, b) \
    asm("add.rn.f32x2 %0, %1, %2;" : "=l"(out) : "l"(a), "l"(b))
#define UNPACK2(lo, hi, v) \
    asm("mov.b64 {%0, %1}, %2;" : "=r"(lo), "=r"(hi) : "l"(v))
#define GBAR(id) \
    asm volatile("bar.sync %0, 64;" :: "r"(id) : "memory")

__device__ int d_perm[BB];

// Rank batches by sequence length (descending): longest chains launch first
// and get dedicated SMs; sorted pairing keeps the two groups in one block
// lifetime-matched.
__global__ void rank_kernel(const int* __restrict__ lens) {
    __shared__ int L[BB];
    const int b = threadIdx.x;
    L[b] = lens[b];
    __syncthreads();
    const int myl = L[b];
    int r = 0;
    #pragma unroll 8
    for (int i = 0; i < BB; ++i) {
        const int li = L[i];
        r += (li > myl) || (li == myl && i < b);
    }
    d_perm[r] = b;
}

// 128 threads = 2 independent batches (group g = tid/64). Warps 0..3 map to
// SMSPs 0..3, so each batch-chain owns a dedicated SMSP pair. Groups sync via
// named barriers (ids g+1) and never lockstep each other.
__global__ __launch_bounds__(128) void crf_kernel(
    const float* __restrict__ inputs,   // [B,T,N]
    const float* __restrict__ trans,    // [N,N]
    const int*   __restrict__ tags,    // [B,T]
    const int*   __restrict__ lens,    // [B]
    float*       __restrict__ out,     // [B] ll, then [N*N] trans copy
    int write_trans)
{
    const int tid  = threadIdx.x;
    const int g    = tid >> 6;            // group 0/1
    const int j    = tid & 63;            // state index
    const int w    = (tid >> 5) & 1;      // warp within group
    const int lane = tid & 31;
    const int bar  = g + 1;               // named barrier id

    const int bb = 2 * blockIdx.x + g;
    const int b  = d_perm[bb];

    __shared__ __align__(16) float s_buf[2][2][NS];  // [group][ping-pong][state]
    __shared__ float red[2][2];                      // [group][warp]

    if (write_trans && blockIdx.x < 32) {
        out[BB + blockIdx.x * 128 + tid] = trans[blockIdx.x * 128 + tid];
    }

    const int len  = lens[b];
    const int last = (len - 1) > 0 ? (len - 1) : 0;

    const int* tg = tags + (size_t)b * TT;
    const float* in_b = inputs + (size_t)b * TT * NS;

    // ---------------- sequence score ----------------
    float sc = 0.f;
    for (int t = j; t < TT; t += NS) {
        if (t < len) {
            int yt = tg[t];
            sc += __ldg(&in_b[(size_t)t * NS + yt]);
            if (t >= 1) sc += __ldg(&trans[tg[t - 1] * NS + yt]);
        }
    }
    #pragma unroll
    for (int o = 16; o; o >>= 1) sc += __shfl_xor_sync(0xffffffffu, sc, o);
    if (lane == 0) red[g][w] = sc;
    GBAR(bar);
    const float seq_score = red[g][0] + red[g][1];
    GBAR(bar);

    // ---------------- E column j, packed f32x2 pairs over i ----------------
    unsigned long long e2[NS / 2];
    #pragma unroll
    for (int k = 0; k < NS / 2; ++k) {
        unsigned lo = __float_as_uint(__expf(__ldg(&trans[(2 * k) * NS + j])));
        unsigned hi = __float_as_uint(__expf(__ldg(&trans[(2 * k + 1) * NS + j])));
        asm("mov.b64 %0, {%1, %2};" : "=l"(e2[k]) : "r"(lo), "r"(hi));
    }

    // ---------------- forward recurrence, scaled linear space ----------------
    const float emit0_0 = __ldg(&in_b[0]);
    float M = emit0_0;
    float s_cur = __expf(in_b[j] - emit0_0);
    s_buf[g][0][j] = s_cur;

    // prefetch pe (= exp(emit_j - emit0)) and emit0, depth 6
    float pe0 = 1.f, pe1 = 1.f, pe2 = 1.f, pe3 = 1.f, pe4 = 1.f, pe5 = 1.f;
    float me0 = 0.f, me1 = 0.f, me2 = 0.f, me3 = 0.f, me4 = 0.f, me5 = 0.f;
    {
        float e0, em;
        if (1 <= last) { e0 = __ldg(&in_b[1 * NS]); em = __ldg(&in_b[1 * NS + j]); pe0 = __expf(em - e0); me0 = e0; }
        if (2 <= last) { e0 = __ldg(&in_b[2 * NS]); em = __ldg(&in_b[2 * NS + j]); pe1 = __expf(em - e0); me1 = e0; }
        if (3 <= last) { e0 = __ldg(&in_b[3 * NS]); em = __ldg(&in_b[3 * NS + j]); pe2 = __expf(em - e0); me2 = e0; }
        if (4 <= last) { e0 = __ldg(&in_b[4 * NS]); em = __ldg(&in_b[4 * NS + j]); pe3 = __expf(em - e0); me3 = e0; }
        if (5 <= last) { e0 = __ldg(&in_b[5 * NS]); em = __ldg(&in_b[5 * NS + j]); pe4 = __expf(em - e0); me4 = e0; }
        if (6 <= last) { e0 = __ldg(&in_b[6 * NS]); em = __ldg(&in_b[6 * NS + j]); pe5 = __expf(em - e0); me5 = e0; }
    }

    int buf = 0;
    for (int t = 1; t <= last; ++t) {
        GBAR(bar);

        // scalar s0 first: rcp + M-update overlap the dot
        const float s0 = s_buf[g][buf][0];
        const float r_inv = __frcp_rn(s0);

        const float pe_c = pe0, me_c = me0;
        pe0 = pe1; me0 = me1; pe1 = pe2; me1 = me2; pe2 = pe3; me2 = me3;
        pe3 = pe4; me3 = me4; pe4 = pe5; me4 = me5;
        const int tn = t + 6;
        if (tn <= last) {
            const float e0 = __ldg(&in_b[(size_t)tn * NS]);
            const float em = __ldg(&in_b[(size_t)tn * NS + j]);
            pe5 = __expf(em - e0);
            me5 = e0;
        }
        M += me_c + __logf(s0);

        const ulonglong2* p4 = (const ulonglong2*)s_buf[g][buf];
        unsigned long long a0 = 0ull, a1 = 0ull, a2 = 0ull, a3 = 0ull;
        #pragma unroll
        for (int m = 0; m < 16; m += 4) {
            ulonglong2 va = p4[m + 0];
            ulonglong2 vb = p4[m + 1];
            ulonglong2 vc = p4[m + 2];
            ulonglong2 vd = p4[m + 3];
            FMA2(a0, va.x, e2[2 * m + 0]); FMA2(a1, va.y, e2[2 * m + 1]);
            FMA2(a2, vb.x, e2[2 * m + 2]); FMA2(a3, vb.y, e2[2 * m + 3]);
            FMA2(a0, vc.x, e2[2 * m + 4]); FMA2(a1, vc.y, e2[2 * m + 5]);
            FMA2(a2, vd.x, e2[2 * m + 6]); FMA2(a3, vd.y, e2[2 * m + 7]);
        }
        unsigned long long c0, c1, c2;
        ADD2(c0, a0, a1);
        ADD2(c1, a2, a3);
        ADD2(c2, c0, c1);
        unsigned lo, hi;
        UNPACK2(lo, hi, c2);
        const float acc = __uint_as_float(lo) + __uint_as_float(hi);

        s_cur = acc * (pe_c * r_inv);
        s_buf[g][buf ^ 1][j] = s_cur;
        buf ^= 1;
    }

    // alpha_j(last) = log(s_j) + M
    const float alpha = __logf(s_cur) + M;

    // ---------------- final logsumexp over states ----------------
    float mx = alpha;
    #pragma unroll
    for (int o = 16; o; o >>= 1)
        mx = fmaxf(mx, __shfl_xor_sync(0xffffffffu, mx, o));
    if (lane == 0) red[g][w] = mx;
    GBAR(bar);
    mx = fmaxf(red[g][0], red[g][1]);
    GBAR(bar);

    float s = __expf(alpha - mx);
    #pragma unroll
    for (int o = 16; o; o >>= 1)
        s += __shfl_xor_sync(0xffffffffu, s, o);
    if (lane == 0) red[g][w] = s;
    GBAR(bar);
    s = red[g][0] + red[g][1];

    if (j == 0) out[b] = seq_score - (mx + __logf(s));
}

extern "C" void kernel_launch(void* const* d_in, const int* in_sizes, int n_in,
                              void* d_out, int out_size) {
    const float* inputs = (const float*)d_in[0];   // [B,T,N] f32
    const float* trans  = (const float*)d_in[1];   // [N,N]   f32
    const int*   tags   = (const int*)d_in[2];     // [B,T]   i32
    const int*   lens   = (const int*)d_in[3];     // [B]     i32
    float* out = (float*)d_out;

    const int write_trans = (out_size >= BB + NS * NS) ? 1 : 0;
    rank_kernel<<<1, BB>>>(lens);
    crf_kernel<<<BB / 2, 128>>>(inputs, trans, tags, lens, out, write_trans);
}